// round 16
// baseline (speedup 1.0000x reference)
#include <cuda_runtime.h>
#include <cuda_bf16.h>
#include <cstdint>

// Problem constants (fixed by the reference)
#define B_ 8
#define S_ 8192
#define H_ 512
#define D_ 768
#define P_ 128
#define M_ (B_ * P_)     // 1024
#define K2_ (H_ / 2)     // 256 packed bf16x2 words per k-row

// Scratch (no allocations allowed), all packed bf16x2 (k even low, k odd high)
__device__ __align__(16) uint32_t g_Ah[M_ * K2_];    // A hi  [m][k2]
__device__ __align__(16) uint32_t g_Al[M_ * K2_];    // A lo  [m][k2]
__device__ __align__(16) uint32_t g_Wh[K2_ * D_];    // W hi  [k2][n]
__device__ __align__(16) uint32_t g_Wl[K2_ * D_];    // W lo  [k2][n]

__device__ __forceinline__ uint32_t bf16pack(float even_e, float odd_e) {
    uint32_t r;   // low 16 = even k, high 16 = odd k
    asm("cvt.rn.bf16x2.f32 %0, %1, %2;" : "=r"(r) : "f"(odd_e), "f"(even_e));
    return r;
}

__device__ __forceinline__ void bsplit(float v, float& h, float& l) {
    h = __bfloat162float(__float2bfloat16_rn(v));
    l = v - h;
}

// ---------------------------------------------------------------------------
// Kernel 1: R8 pool body, parameterized by batch offset. Segment mean via
// binary search -> packed bf16 hi/lo A planes. W split/pack done only by the
// b_off==0 half (6 words per thread over 32768 threads).
// grid = (P_, 4, 2), block = 32. Thread owns 8 consecutive k.
// ---------------------------------------------------------------------------
__global__ void pool_kernel(const float* __restrict__ x,
                            const float* __restrict__ W,
                            const int*   __restrict__ pids,
                            int b_off, int do_w) {
    const int by = blockIdx.y;
    const int b  = b_off + by;
    const int p  = blockIdx.x;
    const int z  = blockIdx.z;
    const int t  = threadIdx.x;

    // ---- W split/pack (first half only): 32768 threads x 6 words = 196608
    if (do_w) {
        const int gtid = ((z * 4 + by) * P_ + p) * 32 + t;   // 0..32767
#pragma unroll
        for (int i = 0; i < 6; ++i) {
            const int idx = i * 32768 + gtid;
            const int k2  = idx / D_;
            const int n   = idx - k2 * D_;
            const float w0 = W[(size_t)(2 * k2) * D_ + n];
            const float w1 = W[(size_t)(2 * k2 + 1) * D_ + n];
            float h0, l0, h1, l1;
            bsplit(w0, h0, l0); bsplit(w1, h1, l1);
            g_Wh[idx] = bf16pack(h0, h1);
            g_Wl[idx] = bf16pack(l0, l1);
        }
    }

    // ---- binary search for patch range
    const int* row = pids + (size_t)b * S_;
    int lo = 0, hi = S_;
    while (lo < hi) { int m = (lo + hi) >> 1; if (__ldg(row + m) < p) lo = m + 1; else hi = m; }
    const int s0 = lo;
    hi = S_;
    while (lo < hi) { int m = (lo + hi) >> 1; if (__ldg(row + m) < p + 1) lo = m + 1; else hi = m; }
    const int s1 = lo;

    // ---- stream & accumulate: thread owns k = 8*kq .. 8*kq+7
    const int kq = z * 32 + t;                       // 0..63
    const float4* xp = (const float4*)x + (size_t)b * S_ * (H_ / 4) + kq * 2;

    float4 a[4][2];
#pragma unroll
    for (int i = 0; i < 4; ++i) {
        a[i][0] = make_float4(0.f, 0.f, 0.f, 0.f);
        a[i][1] = make_float4(0.f, 0.f, 0.f, 0.f);
    }
    int s = s0;
    for (; s + 4 <= s1; s += 4) {
#pragma unroll
        for (int i = 0; i < 4; ++i) {
            const float4 v0 = __ldcs(&xp[(size_t)(s + i) * (H_ / 4)]);
            const float4 v1 = __ldcs(&xp[(size_t)(s + i) * (H_ / 4) + 1]);
            a[i][0].x += v0.x; a[i][0].y += v0.y; a[i][0].z += v0.z; a[i][0].w += v0.w;
            a[i][1].x += v1.x; a[i][1].y += v1.y; a[i][1].z += v1.z; a[i][1].w += v1.w;
        }
    }
    for (; s < s1; ++s) {
        const float4 v0 = __ldcs(&xp[(size_t)s * (H_ / 4)]);
        const float4 v1 = __ldcs(&xp[(size_t)s * (H_ / 4) + 1]);
        a[0][0].x += v0.x; a[0][0].y += v0.y; a[0][0].z += v0.z; a[0][0].w += v0.w;
        a[0][1].x += v1.x; a[0][1].y += v1.y; a[0][1].z += v1.z; a[0][1].w += v1.w;
    }
#pragma unroll
    for (int q = 0; q < 2; ++q) {
        a[0][q].x += a[2][q].x; a[0][q].y += a[2][q].y; a[0][q].z += a[2][q].z; a[0][q].w += a[2][q].w;
        a[1][q].x += a[3][q].x; a[1][q].y += a[3][q].y; a[1][q].z += a[3][q].z; a[1][q].w += a[3][q].w;
        a[0][q].x += a[1][q].x; a[0][q].y += a[1][q].y; a[0][q].z += a[1][q].z; a[0][q].w += a[1][q].w;
    }

    const int   cnt = s1 - s0;
    const float rc  = cnt ? (1.0f / (float)cnt) : 0.0f;   // max(cnt,1) semantics
    float m[8] = { a[0][0].x * rc, a[0][0].y * rc, a[0][0].z * rc, a[0][0].w * rc,
                   a[0][1].x * rc, a[0][1].y * rc, a[0][1].z * rc, a[0][1].w * rc };
    float h[8], l[8];
#pragma unroll
    for (int i = 0; i < 8; ++i) bsplit(m[i], h[i], l[i]);

    const size_t base = (size_t)(b * P_ + p) * K2_ + kq * 4;
    uint4 vh, vl;
    vh.x = bf16pack(h[0], h[1]); vh.y = bf16pack(h[2], h[3]);
    vh.z = bf16pack(h[4], h[5]); vh.w = bf16pack(h[6], h[7]);
    vl.x = bf16pack(l[0], l[1]); vl.y = bf16pack(l[2], l[3]);
    vl.z = bf16pack(l[4], l[5]); vl.w = bf16pack(l[6], l[7]);
    *reinterpret_cast<uint4*>(g_Ah + base) = vh;
    *reinterpret_cast<uint4*>(g_Al + base) = vl;
}

// ---------------------------------------------------------------------------
// Kernel 2: EXACT R8 gemm body, parameterized by m-block offset.
// Block 64x96, BK=64 (8 iters), 512 threads (16 warps 4m x 4n, warp tile
// 16x24). cp.async 16B loads, 2-stage double buffer. grid = (8, 8) per half.
// ---------------------------------------------------------------------------
#define BM 64
#define BN 96
#define BK 64
#define BK2 (BK / 2)     // 32 packed words

#define BUFW  11264
#define AHOF  0
#define ALOF  2304      // 64 * 36
#define WHOF  4608
#define WLOF  7936      // + 32*104
#define ASTR  36        // 32 + 4 pad
#define WSTR  104       // 96 + 8 pad

__device__ __forceinline__ uint32_t smem_u32(const void* p) {
    uint32_t a;
    asm("{ .reg .u64 t; cvta.to.shared.u64 t, %1; cvt.u32.u64 %0, t; }"
        : "=r"(a) : "l"(p));
    return a;
}

__device__ __forceinline__ void cp16(uint32_t saddr, const void* gaddr) {
    asm volatile("cp.async.cg.shared.global [%0], [%1], 16;"
                 :: "r"(saddr), "l"(gaddr));
}

__device__ __forceinline__ void mma_bf16(float* c, const uint32_t* a,
                                         uint32_t b0, uint32_t b1) {
    asm volatile(
        "mma.sync.aligned.m16n8k16.row.col.f32.bf16.bf16.f32 "
        "{%0,%1,%2,%3}, {%4,%5,%6,%7}, {%8,%9}, {%0,%1,%2,%3};"
        : "+f"(c[0]), "+f"(c[1]), "+f"(c[2]), "+f"(c[3])
        : "r"(a[0]), "r"(a[1]), "r"(a[2]), "r"(a[3]), "r"(b0), "r"(b1));
}

__global__ __launch_bounds__(512, 1)
void gemm_kernel(const float* __restrict__ bias, float* __restrict__ out,
                 int mblk_off) {
    extern __shared__ uint32_t smw[];
    const uint32_t sb = smem_u32(smw);

    const int t  = threadIdx.x;          // 0..511
    const int w  = t >> 5;
    const int ln = t & 31;
    const int g  = ln >> 2;
    const int tg = ln & 3;
    const int wm = w & 3;                // 16-row slice
    const int wn = w >> 2;               // 24-col slice
    const int m0 = (mblk_off + blockIdx.y) * BM;
    const int n0 = blockIdx.x * BN;

    const int ar  = t >> 3;              // A row 0..63
    const int aju = t & 7;               // A 16B unit 0..7

    float acc[3][4] = {};

    auto load_chunk = [&](int c) {
        const int kb2 = c * BK2;
        {   // A: 64 rows x 8 u4 per plane
            const uint32_t so = (ar * ASTR + aju * 4) * 4;
            const size_t  go = (size_t)(m0 + ar) * K2_ + kb2 + aju * 4;
            cp16(sb + ((c & 1) * BUFW + AHOF) * 4 + so, g_Ah + go);
            cp16(sb + ((c & 1) * BUFW + ALOF) * 4 + so, g_Al + go);
        }
        {   // W: 32 rows x 24 u4 per plane (768 u4)
            const int r = t / 24, cb = t % 24;
            const uint32_t so = (r * WSTR + cb * 4) * 4;
            const size_t  go = (size_t)(kb2 + r) * D_ + n0 + cb * 4;
            cp16(sb + ((c & 1) * BUFW + WHOF) * 4 + so, g_Wh + go);
            cp16(sb + ((c & 1) * BUFW + WLOF) * 4 + so, g_Wl + go);
        }
        if (t < 256) {
            const int i2 = t + 512;
            const int r = i2 / 24, cb = i2 % 24;
            const uint32_t so = (r * WSTR + cb * 4) * 4;
            const size_t  go = (size_t)(kb2 + r) * D_ + n0 + cb * 4;
            cp16(sb + ((c & 1) * BUFW + WHOF) * 4 + so, g_Wh + go);
            cp16(sb + ((c & 1) * BUFW + WLOF) * 4 + so, g_Wl + go);
        }
    };

    load_chunk(0);
    asm volatile("cp.async.commit_group;" ::: "memory");

    const int NCH = H_ / BK;             // 8
    for (int c = 0; c < NCH; ++c) {
        if (c + 1 < NCH) {
            load_chunk(c + 1);
            asm volatile("cp.async.commit_group;" ::: "memory");
            asm volatile("cp.async.wait_group 1;" ::: "memory");
        } else {
            asm volatile("cp.async.wait_group 0;" ::: "memory");
        }
        __syncthreads();

        const uint32_t* Ah = smw + (c & 1) * BUFW + AHOF;
        const uint32_t* Al = smw + (c & 1) * BUFW + ALOF;
        const uint32_t* Wh = smw + (c & 1) * BUFW + WHOF;
        const uint32_t* Wl = smw + (c & 1) * BUFW + WLOF;
        const int r = wm * 16 + g;

#pragma unroll
        for (int sl = 0; sl < 4; ++sl) {     // 4 k16-slabs per chunk
            const int cc = sl * 8 + tg;
            uint32_t ah[4], al[4];
            ah[0] = Ah[r * ASTR + cc];           al[0] = Al[r * ASTR + cc];
            ah[1] = Ah[(r + 8) * ASTR + cc];     al[1] = Al[(r + 8) * ASTR + cc];
            ah[2] = Ah[r * ASTR + cc + 4];       al[2] = Al[r * ASTR + cc + 4];
            ah[3] = Ah[(r + 8) * ASTR + cc + 4]; al[3] = Al[(r + 8) * ASTR + cc + 4];
#pragma unroll
            for (int nf = 0; nf < 3; ++nf) {
                const int n = wn * 24 + nf * 8 + g;
                const uint32_t bh0 = Wh[cc * WSTR + n];
                const uint32_t bh1 = Wh[(cc + 4) * WSTR + n];
                const uint32_t bl0 = Wl[cc * WSTR + n];
                const uint32_t bl1 = Wl[(cc + 4) * WSTR + n];
                mma_bf16(acc[nf], ah, bh0, bh1);   // hi*hi
                mma_bf16(acc[nf], al, bh0, bh1);   // lo*hi
                mma_bf16(acc[nf], ah, bl0, bl1);   // hi*lo
            }
        }
        __syncthreads();                 // buffer may be overwritten next iter
    }

    // ---- epilogue
#pragma unroll
    for (int nf = 0; nf < 3; ++nf) {
        const int ncol = n0 + wn * 24 + nf * 8 + 2 * tg;
        const float2 bv = *(const float2*)(bias + ncol);
        const int mrow = m0 + wm * 16 + g;
        float2 o0, o1;
        o0.x = acc[nf][0] + bv.x;  o0.y = acc[nf][1] + bv.y;
        o1.x = acc[nf][2] + bv.x;  o1.y = acc[nf][3] + bv.y;
        *(float2*)(out + (size_t)mrow * D_ + ncol)       = o0;
        *(float2*)(out + (size_t)(mrow + 8) * D_ + ncol) = o1;
    }
}

// ---------------------------------------------------------------------------
// Launch: fork-join overlap. pool_A (b0-3 + W) -> gemm_half1 on the main
// stream; pool_B (b4-7) concurrently on s2; join before gemm_half2.
// Streams/events created once on the first (uncaptured) correctness call.
// ---------------------------------------------------------------------------
extern "C" void kernel_launch(void* const* d_in, const int* in_sizes, int n_in,
                              void* d_out, int out_size) {
    const float* x    = (const float*)d_in[0];   // byte_hiddens [B,S,H]
    const float* W    = (const float*)d_in[1];   // W_proj [H,D]
    const float* bias = (const float*)d_in[2];   // b_proj [D]
    const int*   pids = (const int*)  d_in[3];   // patch_ids [B,S]
    float*       out  = (float*)d_out;           // [B,P,D]

    static cudaStream_t s2 = nullptr;
    static cudaEvent_t  eA = nullptr, eB = nullptr;
    static bool attr_done = false;
    if (!s2) {
        cudaStreamCreateWithFlags(&s2, cudaStreamNonBlocking);
        cudaEventCreateWithFlags(&eA, cudaEventDisableTiming);
        cudaEventCreateWithFlags(&eB, cudaEventDisableTiming);
    }
    const int smem_bytes = 2 * BUFW * 4;         // 90112
    if (!attr_done) {
        cudaFuncSetAttribute(gemm_kernel,
                             cudaFuncAttributeMaxDynamicSharedMemorySize,
                             smem_bytes);
        attr_done = true;
    }

    // pool_A: batches 0-3 + W split (main stream)
    pool_kernel<<<dim3(P_, 4, 2), 32>>>(x, W, pids, 0, 1);
    cudaEventRecord(eA, 0);
    cudaStreamWaitEvent(s2, eA, 0);
    // pool_B: batches 4-7 (s2, concurrent with gemm_half1)
    pool_kernel<<<dim3(P_, 4, 2), 32, 0, s2>>>(x, W, pids, 4, 0);
    cudaEventRecord(eB, s2);
    // gemm_half1: m rows 0..511 (needs pool_A only)
    gemm_kernel<<<dim3(D_ / BN, 8), 512, smem_bytes>>>(bias, out, 0);
    // join pool_B, then gemm_half2: m rows 512..1023
    cudaStreamWaitEvent(0, eB, 0);
    gemm_kernel<<<dim3(D_ / BN, 8), 512, smem_bytes>>>(bias, out, 8);
}

// round 17
// speedup vs baseline: 1.6371x; 1.6371x over previous
#include <cuda_runtime.h>
#include <cuda_bf16.h>
#include <cstdint>

// Problem constants (fixed by the reference)
#define B_ 8
#define S_ 8192
#define H_ 512
#define D_ 768
#define P_ 128
#define M_ (B_ * P_)     // 1024
#define K2_ (H_ / 2)     // 256 packed bf16x2 words per k-row

// Scratch (no allocations allowed), all packed bf16x2 (k even low, k odd high)
__device__ __align__(16) uint32_t g_Ah[M_ * K2_];    // A hi  [m][k2]
__device__ __align__(16) uint32_t g_Al[M_ * K2_];    // A lo  [m][k2]
__device__ __align__(16) uint32_t g_Wh[K2_ * D_];    // W hi  [k2][n]
__device__ __align__(16) uint32_t g_Wl[K2_ * D_];    // W lo  [k2][n]

__device__ __forceinline__ uint32_t bf16pack(float even_e, float odd_e) {
    uint32_t r;   // low 16 = even k, high 16 = odd k
    asm("cvt.rn.bf16x2.f32 %0, %1, %2;" : "=r"(r) : "f"(odd_e), "f"(even_e));
    return r;
}

__device__ __forceinline__ void bsplit(float v, float& h, float& l) {
    h = __bfloat162float(__float2bfloat16_rn(v));
    l = v - h;
}

// ---------------------------------------------------------------------------
// Kernel 0: W [K][N] f32 -> packed bf16 hi/lo planes [k2][n].
// 192 blocks x 256 threads x 4 words, fully coalesced.
// ---------------------------------------------------------------------------
__global__ void prep_w(const float* __restrict__ W) {
    const int base = blockIdx.x * 1024 + threadIdx.x;
#pragma unroll
    for (int j = 0; j < 4; ++j) {
        const int idx = base + j * 256;
        const int k2  = idx / D_;
        const int n   = idx - k2 * D_;
        const float w0 = W[(size_t)(2 * k2) * D_ + n];
        const float w1 = W[(size_t)(2 * k2 + 1) * D_ + n];
        float h0, l0, h1, l1;
        bsplit(w0, h0, l0); bsplit(w1, h1, l1);
        g_Wh[idx] = bf16pack(h0, h1);
        g_Wl[idx] = bf16pack(l0, l1);
    }
}

// ---------------------------------------------------------------------------
// Kernel 1: EXACT R5 pool (measured 24.3us): segment mean via binary search,
// grid (P_, B_, 2), block 64, thread owns one float4 column, 8-deep unroll,
// packed bf16 hi/lo output. NO other work in this kernel.
// ---------------------------------------------------------------------------
__global__ void pool_kernel(const float* __restrict__ x,
                            const int*   __restrict__ pids) {
    const int b  = blockIdx.y;
    const int p  = blockIdx.x;
    const int z  = blockIdx.z;
    const int t  = threadIdx.x;
    const int hq = z * 64 + t;            // float4 column 0..127

    // ---- binary search for patch range
    const int* row = pids + (size_t)b * S_;
    int lo = 0, hi = S_;
    while (lo < hi) { int m = (lo + hi) >> 1; if (__ldg(row + m) < p) lo = m + 1; else hi = m; }
    const int s0 = lo;
    hi = S_;
    while (lo < hi) { int m = (lo + hi) >> 1; if (__ldg(row + m) < p + 1) lo = m + 1; else hi = m; }
    const int s1 = lo;

    // ---- stream & accumulate (8 outstanding float4 loads)
    const float4* xp = (const float4*)x + (size_t)b * S_ * (H_ / 4) + hq;

    float4 a[8];
#pragma unroll
    for (int i = 0; i < 8; ++i) a[i] = make_float4(0.f, 0.f, 0.f, 0.f);

    int s = s0;
    for (; s + 8 <= s1; s += 8) {
#pragma unroll
        for (int i = 0; i < 8; ++i) {
            const float4 v = __ldcs(&xp[(size_t)(s + i) * (H_ / 4)]);
            a[i].x += v.x; a[i].y += v.y; a[i].z += v.z; a[i].w += v.w;
        }
    }
    for (; s < s1; ++s) {
        const float4 v = __ldcs(&xp[(size_t)s * (H_ / 4)]);
        a[0].x += v.x; a[0].y += v.y; a[0].z += v.z; a[0].w += v.w;
    }

#pragma unroll
    for (int i = 0; i < 4; ++i) {
        a[i].x += a[i + 4].x; a[i].y += a[i + 4].y;
        a[i].z += a[i + 4].z; a[i].w += a[i + 4].w;
    }
    a[0].x += a[2].x; a[0].y += a[2].y; a[0].z += a[2].z; a[0].w += a[2].w;
    a[1].x += a[3].x; a[1].y += a[3].y; a[1].z += a[3].z; a[1].w += a[3].w;

    const int   cnt = s1 - s0;
    const float rc  = cnt ? (1.0f / (float)cnt) : 0.0f;   // max(cnt,1) semantics
    const float m0v = (a[0].x + a[1].x) * rc;
    const float m1v = (a[0].y + a[1].y) * rc;
    const float m2v = (a[0].z + a[1].z) * rc;
    const float m3v = (a[0].w + a[1].w) * rc;

    float h0,l0,h1,l1,h2,l2,h3,l3;
    bsplit(m0v,h0,l0); bsplit(m1v,h1,l1);
    bsplit(m2v,h2,l2); bsplit(m3v,h3,l3);

    const size_t base = (size_t)(b * P_ + p) * K2_ + hq * 2;
    uint2 vh, vl;
    vh.x = bf16pack(h0, h1); vh.y = bf16pack(h2, h3);
    vl.x = bf16pack(l0, l1); vl.y = bf16pack(l2, l3);
    *reinterpret_cast<uint2*>(g_Ah + base) = vh;
    *reinterpret_cast<uint2*>(g_Al + base) = vl;
}

// ---------------------------------------------------------------------------
// Kernel 2: EXACT R8 gemm (measured 14.9us): out = A @ W + bias, bf16
// 3-product split, everything pre-packed. Block 64x96, BK=64 (8 iters),
// 512 threads (16 warps 4m x 4n, warp tile 16x24), cp.async, double buffer.
// grid = (8, 16) = 128 CTAs, single wave.
// ---------------------------------------------------------------------------
#define BM 64
#define BN 96
#define BK 64
#define BK2 (BK / 2)     // 32 packed words

#define BUFW  11264
#define AHOF  0
#define ALOF  2304      // 64 * 36
#define WHOF  4608
#define WLOF  7936      // + 32*104
#define ASTR  36        // 32 + 4 pad
#define WSTR  104       // 96 + 8 pad

__device__ __forceinline__ uint32_t smem_u32(const void* p) {
    uint32_t a;
    asm("{ .reg .u64 t; cvta.to.shared.u64 t, %1; cvt.u32.u64 %0, t; }"
        : "=r"(a) : "l"(p));
    return a;
}

__device__ __forceinline__ void cp16(uint32_t saddr, const void* gaddr) {
    asm volatile("cp.async.cg.shared.global [%0], [%1], 16;"
                 :: "r"(saddr), "l"(gaddr));
}

__device__ __forceinline__ void mma_bf16(float* c, const uint32_t* a,
                                         uint32_t b0, uint32_t b1) {
    asm volatile(
        "mma.sync.aligned.m16n8k16.row.col.f32.bf16.bf16.f32 "
        "{%0,%1,%2,%3}, {%4,%5,%6,%7}, {%8,%9}, {%0,%1,%2,%3};"
        : "+f"(c[0]), "+f"(c[1]), "+f"(c[2]), "+f"(c[3])
        : "r"(a[0]), "r"(a[1]), "r"(a[2]), "r"(a[3]), "r"(b0), "r"(b1));
}

__global__ __launch_bounds__(512, 1)
void gemm_kernel(const float* __restrict__ bias, float* __restrict__ out) {
    extern __shared__ uint32_t smw[];
    const uint32_t sb = smem_u32(smw);

    const int t  = threadIdx.x;          // 0..511
    const int w  = t >> 5;
    const int ln = t & 31;
    const int g  = ln >> 2;
    const int tg = ln & 3;
    const int wm = w & 3;                // 16-row slice
    const int wn = w >> 2;               // 24-col slice
    const int m0 = blockIdx.y * BM;
    const int n0 = blockIdx.x * BN;

    const int ar  = t >> 3;              // A row 0..63
    const int aju = t & 7;               // A 16B unit 0..7

    float acc[3][4] = {};

    auto load_chunk = [&](int c) {
        const int kb2 = c * BK2;
        {   // A: 64 rows x 8 u4 per plane
            const uint32_t so = (ar * ASTR + aju * 4) * 4;
            const size_t  go = (size_t)(m0 + ar) * K2_ + kb2 + aju * 4;
            cp16(sb + ((c & 1) * BUFW + AHOF) * 4 + so, g_Ah + go);
            cp16(sb + ((c & 1) * BUFW + ALOF) * 4 + so, g_Al + go);
        }
        {   // W: 32 rows x 24 u4 per plane (768 u4)
            const int r = t / 24, cb = t % 24;
            const uint32_t so = (r * WSTR + cb * 4) * 4;
            const size_t  go = (size_t)(kb2 + r) * D_ + n0 + cb * 4;
            cp16(sb + ((c & 1) * BUFW + WHOF) * 4 + so, g_Wh + go);
            cp16(sb + ((c & 1) * BUFW + WLOF) * 4 + so, g_Wl + go);
        }
        if (t < 256) {
            const int i2 = t + 512;
            const int r = i2 / 24, cb = i2 % 24;
            const uint32_t so = (r * WSTR + cb * 4) * 4;
            const size_t  go = (size_t)(kb2 + r) * D_ + n0 + cb * 4;
            cp16(sb + ((c & 1) * BUFW + WHOF) * 4 + so, g_Wh + go);
            cp16(sb + ((c & 1) * BUFW + WLOF) * 4 + so, g_Wl + go);
        }
    };

    load_chunk(0);
    asm volatile("cp.async.commit_group;" ::: "memory");

    const int NCH = H_ / BK;             // 8
    for (int c = 0; c < NCH; ++c) {
        if (c + 1 < NCH) {
            load_chunk(c + 1);
            asm volatile("cp.async.commit_group;" ::: "memory");
            asm volatile("cp.async.wait_group 1;" ::: "memory");
        } else {
            asm volatile("cp.async.wait_group 0;" ::: "memory");
        }
        __syncthreads();

        const uint32_t* Ah = smw + (c & 1) * BUFW + AHOF;
        const uint32_t* Al = smw + (c & 1) * BUFW + ALOF;
        const uint32_t* Wh = smw + (c & 1) * BUFW + WHOF;
        const uint32_t* Wl = smw + (c & 1) * BUFW + WLOF;
        const int r = wm * 16 + g;

#pragma unroll
        for (int sl = 0; sl < 4; ++sl) {     // 4 k16-slabs per chunk
            const int cc = sl * 8 + tg;
            uint32_t ah[4], al[4];
            ah[0] = Ah[r * ASTR + cc];           al[0] = Al[r * ASTR + cc];
            ah[1] = Ah[(r + 8) * ASTR + cc];     al[1] = Al[(r + 8) * ASTR + cc];
            ah[2] = Ah[r * ASTR + cc + 4];       al[2] = Al[r * ASTR + cc + 4];
            ah[3] = Ah[(r + 8) * ASTR + cc + 4]; al[3] = Al[(r + 8) * ASTR + cc + 4];
#pragma unroll
            for (int nf = 0; nf < 3; ++nf) {
                const int n = wn * 24 + nf * 8 + g;
                const uint32_t bh0 = Wh[cc * WSTR + n];
                const uint32_t bh1 = Wh[(cc + 4) * WSTR + n];
                const uint32_t bl0 = Wl[cc * WSTR + n];
                const uint32_t bl1 = Wl[(cc + 4) * WSTR + n];
                mma_bf16(acc[nf], ah, bh0, bh1);   // hi*hi
                mma_bf16(acc[nf], al, bh0, bh1);   // lo*hi
                mma_bf16(acc[nf], ah, bl0, bl1);   // hi*lo
            }
        }
        __syncthreads();                 // buffer may be overwritten next iter
    }

    // ---- epilogue
#pragma unroll
    for (int nf = 0; nf < 3; ++nf) {
        const int ncol = n0 + wn * 24 + nf * 8 + 2 * tg;
        const float2 bv = *(const float2*)(bias + ncol);
        const int mrow = m0 + wm * 16 + g;
        float2 o0, o1;
        o0.x = acc[nf][0] + bv.x;  o0.y = acc[nf][1] + bv.y;
        o1.x = acc[nf][2] + bv.x;  o1.y = acc[nf][3] + bv.y;
        *(float2*)(out + (size_t)mrow * D_ + ncol)       = o0;
        *(float2*)(out + (size_t)(mrow + 8) * D_ + ncol) = o1;
    }
}

// ---------------------------------------------------------------------------
// Launch: three serial kernels — prep_w, bare pool, gemm.
// ---------------------------------------------------------------------------
extern "C" void kernel_launch(void* const* d_in, const int* in_sizes, int n_in,
                              void* d_out, int out_size) {
    const float* x    = (const float*)d_in[0];   // byte_hiddens [B,S,H]
    const float* W    = (const float*)d_in[1];   // W_proj [H,D]
    const float* bias = (const float*)d_in[2];   // b_proj [D]
    const int*   pids = (const int*)  d_in[3];   // patch_ids [B,S]
    float*       out  = (float*)d_out;           // [B,P,D]

    const int smem_bytes = 2 * BUFW * 4;         // 90112
    cudaFuncSetAttribute(gemm_kernel, cudaFuncAttributeMaxDynamicSharedMemorySize,
                         smem_bytes);

    prep_w<<<192, 256>>>(W);
    pool_kernel<<<dim3(P_, B_, 2), 64>>>(x, pids);
    gemm_kernel<<<dim3(D_ / BN, M_ / BM), 512, smem_bytes>>>(bias, out);
}